// round 14
// baseline (speedup 1.0000x reference)
#include <cuda_runtime.h>
#include <math.h>
#include <stdint.h>

// ---------------------------------------------------------------------------
// Problem constants
// ---------------------------------------------------------------------------
#define N_      4
#define T_      2048
#define C_      1024        // = H*HS = attention dim = model dim
#define MTOT    (N_ * T_)   // 8192 rows for the GEMMs
#define NCHUNK  128
#define CS      (T_ / NCHUNK)   // 16 timesteps per chunk

// ---------------------------------------------------------------------------
// Scratch (allocation-free: __device__ globals)
// ---------------------------------------------------------------------------
__device__ float g_XR[MTOT * C_];   // tf32-rounded interpolated inputs
__device__ float g_XK[MTOT * C_];
__device__ float g_XV[MTOT * C_];
__device__ float g_R [MTOT * C_];
__device__ float g_K [MTOT * C_];
__device__ float g_V [MTOT * C_];
__device__ float g_G [MTOT * C_];   // tf32-rounded sigmoid(R)*WKV
__device__ float g_Wc[4 * C_ * C_]; // tf32-rounded Wr|Wk|Wv|Wo
__device__ float g_SA[N_ * NCHUNK * C_];
__device__ float g_SB[N_ * NCHUNK * C_];

// ---------------------------------------------------------------------------
// Helpers
// ---------------------------------------------------------------------------
__device__ __forceinline__ float clip_wk(float x) {
    return fminf(fmaxf(x, -20.0f), 10.0f);
}

__device__ __forceinline__ float f2tf32f(float f) {
    uint32_t u;
    asm("cvt.rna.tf32.f32 %0, %1;" : "=r"(u) : "f"(f));
    return __uint_as_float(u);
}

__device__ __forceinline__ void mma_tf32(float* d, const uint32_t* a, const uint32_t* b) {
    asm volatile(
        "mma.sync.aligned.m16n8k8.row.col.f32.tf32.tf32.f32 "
        "{%0,%1,%2,%3}, {%4,%5,%6,%7}, {%8,%9}, {%0,%1,%2,%3};\n"
        : "+f"(d[0]), "+f"(d[1]), "+f"(d[2]), "+f"(d[3])
        : "r"(a[0]), "r"(a[1]), "r"(a[2]), "r"(a[3]), "r"(b[0]), "r"(b[1]));
}

__device__ __forceinline__ void cp16(float* smem_dst, const float* gsrc) {
    uint32_t s = (uint32_t)__cvta_generic_to_shared(smem_dst);
    asm volatile("cp.async.cg.shared.global [%0], [%1], 16;\n" :: "r"(s), "l"(gsrc));
}
__device__ __forceinline__ void cp_commit() {
    asm volatile("cp.async.commit_group;\n");
}
__device__ __forceinline__ void cp_wait1() {
    asm volatile("cp.async.wait_group 1;\n");
}
__device__ __forceinline__ void cp_wait0() {
    asm volatile("cp.async.wait_group 0;\n");
}

// ---------------------------------------------------------------------------
// Prep 1: time interpolation + tf32 rounding (float4)
// ---------------------------------------------------------------------------
__global__ void interp_prep(const float* __restrict__ x,
                            float er, float omr,
                            float ek, float omk,
                            float ev, float omv)
{
    int idx4 = blockIdx.x * blockDim.x + threadIdx.x;
    if (idx4 >= MTOT * C_ / 4) return;
    size_t base = (size_t)idx4 * 4;
    int t = (int)((base / C_) % T_);

    float4 p  = make_float4(0.f, 0.f, 0.f, 0.f);
    float4 nx = make_float4(0.f, 0.f, 0.f, 0.f);
    if (t > 0)      p  = *reinterpret_cast<const float4*>(x + base - C_);
    if (t < T_ - 1) nx = *reinterpret_cast<const float4*>(x + base + C_);

    float4 r, k, v;
    r.x = f2tf32f(er * p.x + omr * nx.x);  r.y = f2tf32f(er * p.y + omr * nx.y);
    r.z = f2tf32f(er * p.z + omr * nx.z);  r.w = f2tf32f(er * p.w + omr * nx.w);
    k.x = f2tf32f(ek * p.x + omk * nx.x);  k.y = f2tf32f(ek * p.y + omk * nx.y);
    k.z = f2tf32f(ek * p.z + omk * nx.z);  k.w = f2tf32f(ek * p.w + omk * nx.w);
    v.x = f2tf32f(ev * p.x + omv * nx.x);  v.y = f2tf32f(ev * p.y + omv * nx.y);
    v.z = f2tf32f(ev * p.z + omv * nx.z);  v.w = f2tf32f(ev * p.w + omv * nx.w);

    *reinterpret_cast<float4*>(g_XR + base) = r;
    *reinterpret_cast<float4*>(g_XK + base) = k;
    *reinterpret_cast<float4*>(g_XV + base) = v;
}

// ---------------------------------------------------------------------------
// Prep 2: round weights to tf32.  blockIdx.y selects which weight.
// ---------------------------------------------------------------------------
__global__ void weight_prep(const float* __restrict__ w0, const float* __restrict__ w1,
                            const float* __restrict__ w2, const float* __restrict__ w3)
{
    int idx4 = blockIdx.x * blockDim.x + threadIdx.x;
    if (idx4 >= C_ * C_ / 4) return;
    const float* src = (blockIdx.y == 0) ? w0 : (blockIdx.y == 1) ? w1
                     : (blockIdx.y == 2) ? w2 : w3;
    size_t base = (size_t)idx4 * 4;
    float4 v = *reinterpret_cast<const float4*>(src + base);
    v.x = f2tf32f(v.x); v.y = f2tf32f(v.y); v.z = f2tf32f(v.z); v.w = f2tf32f(v.w);
    *reinterpret_cast<float4*>(g_Wc + (size_t)blockIdx.y * C_ * C_ + base) = v;
}

// ---------------------------------------------------------------------------
// TF32 tensor-core GEMM (NT), cp.async 3-stage ring, one barrier per K-tile.
//   C[m,j] = sum_k A[m,k]*W[j,k] + bias[j]
//   A, W already tf32-rounded.
//   CTA tile 128x256, BK=32; 8 warps in 2x4 grid of 64x64 warp tiles
//   (4x8 m16n8k8 fragments, 128 acc regs/lane).
//   blockIdx.z selects among up to 3 fused (A, W, bias, Cout) problem sets.
// ---------------------------------------------------------------------------
#define BM 128
#define BN 256
#define BK 32
#define LDSS 36                  // 36 floats = 144B row stride: 16B aligned, conflict-free
#define A_SZ (128 * LDSS)
#define B_SZ (256 * LDSS)
#define STAGE_SZ (A_SZ + B_SZ)   // 13824 floats = 54KB
#define NSTAGE 3
#define NKT (C_ / BK)            // 32
#define GEMM_SMEM (NSTAGE * STAGE_SZ * (int)sizeof(float))   // 165888 B

__global__ __launch_bounds__(256, 1)
void gemm_tf32(const float* __restrict__ A0, const float* __restrict__ A1,
               const float* __restrict__ A2,
               const float* __restrict__ Wc,
               const float* __restrict__ b0, const float* __restrict__ b1,
               const float* __restrict__ b2,
               float* __restrict__ C0, float* __restrict__ C1,
               float* __restrict__ C2,
               int wsel)
{
    extern __shared__ __align__(16) float sm[];   // [NSTAGE][STAGE_SZ]

    const int z = blockIdx.z;
    const float* A    = (z == 0) ? A0 : (z == 1) ? A1 : A2;
    const float* W    = Wc + (size_t)(wsel + z) * C_ * C_;
    const float* bias = (z == 0) ? b0 : (z == 1) ? b1 : b2;
    float*       Cout = (z == 0) ? C0 : (z == 1) ? C1 : C2;

    const int K  = C_;
    const int Nn = C_;

    const int tid    = threadIdx.x;
    const int bm     = blockIdx.y * BM;
    const int bn     = blockIdx.x * BN;
    const int warpId = tid >> 5;
    const int lane   = tid & 31;
    const int g      = lane >> 2;           // 0..7
    const int t4     = lane & 3;            // 0..3
    const int wr     = (warpId >> 2) * 64;  // warp row offset (2 bands)
    const int wc     = (warpId & 3) * 64;   // warp col offset (4 bands)

    const int lrow = tid >> 3;              // 0..31
    const int lcol = (tid & 7) * 4;         // 0,4,...,28

    const float* Abase = A + (size_t)(bm + lrow) * K + lcol;
    const float* Bbase = W + (size_t)(bn + lrow) * K + lcol;
    float* Asd = sm + lrow * LDSS + lcol;
    float* Bsd = sm + A_SZ + lrow * LDSS + lcol;

    float acc[4][8][4];
    #pragma unroll
    for (int i = 0; i < 4; i++)
        #pragma unroll
        for (int j = 0; j < 8; j++)
            #pragma unroll
            for (int q = 0; q < 4; q++)
                acc[i][j][q] = 0.0f;

    auto load_stage = [&](int s, int kt) {
        const size_t ko = (size_t)kt * BK;
        #pragma unroll
        for (int i = 0; i < 4; i++)
            cp16(Asd + s * STAGE_SZ + i * 32 * LDSS, Abase + ko + i * 32 * (size_t)K);
        #pragma unroll
        for (int i = 0; i < 8; i++)
            cp16(Bsd + s * STAGE_SZ + i * 32 * LDSS, Bbase + ko + i * 32 * (size_t)K);
        cp_commit();
    };

    // prologue: stages 0,1
    load_stage(0, 0);
    load_stage(1, 1);

    int cur = 0;   // stage holding tile kt
    for (int kt = 0; kt < NKT; kt++) {
        if (kt + 1 < NKT) cp_wait1();
        else              cp_wait0();
        __syncthreads();   // single barrier: data visible AND stage (kt+2)%3 free

        if (kt + 2 < NKT) {
            int nst = cur + 2; if (nst >= NSTAGE) nst -= NSTAGE;
            load_stage(nst, kt + 2);
        }

        const float* Ab = sm + cur * STAGE_SZ;
        const float* Bb = sm + cur * STAGE_SZ + A_SZ;

        #pragma unroll
        for (int kk = 0; kk < 4; kk++) {
            const int kb = kk * 8;
            uint32_t afr[4][4];
            uint32_t bfr[8][2];
            #pragma unroll
            for (int mt = 0; mt < 4; mt++) {
                const int r0 = wr + mt * 16;
                afr[mt][0] = __float_as_uint(Ab[(r0 + g    ) * LDSS + kb + t4    ]);
                afr[mt][1] = __float_as_uint(Ab[(r0 + g + 8) * LDSS + kb + t4    ]);
                afr[mt][2] = __float_as_uint(Ab[(r0 + g    ) * LDSS + kb + t4 + 4]);
                afr[mt][3] = __float_as_uint(Ab[(r0 + g + 8) * LDSS + kb + t4 + 4]);
            }
            #pragma unroll
            for (int nt = 0; nt < 8; nt++) {
                const int c0 = wc + nt * 8;
                bfr[nt][0] = __float_as_uint(Bb[(c0 + g) * LDSS + kb + t4    ]);
                bfr[nt][1] = __float_as_uint(Bb[(c0 + g) * LDSS + kb + t4 + 4]);
            }
            #pragma unroll
            for (int mt = 0; mt < 4; mt++)
                #pragma unroll
                for (int nt = 0; nt < 8; nt++)
                    mma_tf32(acc[mt][nt], afr[mt], bfr[nt]);
        }

        cur++; if (cur >= NSTAGE) cur = 0;
    }

    // epilogue: bias + store
    #pragma unroll
    for (int mt = 0; mt < 4; mt++) {
        const int row = bm + wr + mt * 16 + g;
        #pragma unroll
        for (int nt = 0; nt < 8; nt++) {
            const int col = bn + wc + nt * 8 + t4 * 2;
            const float b0v = bias[col];
            const float b1v = bias[col + 1];
            float2 v0 = make_float2(acc[mt][nt][0] + b0v, acc[mt][nt][1] + b1v);
            float2 v1 = make_float2(acc[mt][nt][2] + b0v, acc[mt][nt][3] + b1v);
            *reinterpret_cast<float2*>(Cout + (size_t)row * Nn + col) = v0;
            *reinterpret_cast<float2*>(Cout + (size_t)(row + 8) * Nn + col) = v1;
        }
    }
}

// ---------------------------------------------------------------------------
// WKV recurrence (chunk-parallel cumsum, 3 passes).  256 threads, 4 ch/thread.
// ---------------------------------------------------------------------------
__global__ __launch_bounds__(256)
void wkv_partial(const float* __restrict__ td)
{
    const int c4    = threadIdx.x * 4;
    const int chunk = blockIdx.x;
    const int n     = blockIdx.y;

    float4 wv = *reinterpret_cast<const float4*>(td + c4);
    wv.x = fmaxf(wv.x, 0.f); wv.y = fmaxf(wv.y, 0.f);
    wv.z = fmaxf(wv.z, 0.f); wv.w = fmaxf(wv.w, 0.f);

    const int t0 = chunk * CS;
    const size_t base = ((size_t)n * T_ + t0) * C_ + c4;

    float4 sa = make_float4(0.f, 0.f, 0.f, 0.f);
    float4 sb = make_float4(0.f, 0.f, 0.f, 0.f);

    #pragma unroll 4
    for (int i = 0; i < CS; i++) {
        const float tr = (float)(T_ - 1 - (t0 + i));
        float4 k = *reinterpret_cast<const float4*>(g_K + base + (size_t)i * C_);
        float4 v = *reinterpret_cast<const float4*>(g_V + base + (size_t)i * C_);
        float ex = __expf(clip_wk(fmaf(-wv.x, tr, k.x)));
        float ey = __expf(clip_wk(fmaf(-wv.y, tr, k.y)));
        float ez = __expf(clip_wk(fmaf(-wv.z, tr, k.z)));
        float ew = __expf(clip_wk(fmaf(-wv.w, tr, k.w)));
        sa.x = fmaf(ex, v.x, sa.x); sb.x += ex;
        sa.y = fmaf(ey, v.y, sa.y); sb.y += ey;
        sa.z = fmaf(ez, v.z, sa.z); sb.z += ez;
        sa.w = fmaf(ew, v.w, sa.w); sb.w += ew;
    }
    size_t o = ((size_t)n * NCHUNK + chunk) * C_ + c4;
    *reinterpret_cast<float4*>(g_SA + o) = sa;
    *reinterpret_cast<float4*>(g_SB + o) = sb;
}

__global__ void wkv_scan()
{
    int idx = blockIdx.x * blockDim.x + threadIdx.x;   // over N_*C_
    if (idx >= N_ * C_) return;
    int n = idx / C_;
    int c = idx % C_;
    float ra = 0.0f, rb = 0.0f;
    for (int ch = 0; ch < NCHUNK; ch++) {
        size_t o = ((size_t)n * NCHUNK + ch) * C_ + c;
        float ta = g_SA[o], tb = g_SB[o];
        g_SA[o] = ra;                 // exclusive prefix
        g_SB[o] = rb;
        ra += ta;
        rb += tb;
    }
}

__global__ __launch_bounds__(256)
void wkv_final(const float* __restrict__ td, const float* __restrict__ U)
{
    const int c4    = threadIdx.x * 4;
    const int chunk = blockIdx.x;
    const int n     = blockIdx.y;

    float4 wv = *reinterpret_cast<const float4*>(td + c4);
    wv.x = fmaxf(wv.x, 0.f); wv.y = fmaxf(wv.y, 0.f);
    wv.z = fmaxf(wv.z, 0.f); wv.w = fmaxf(wv.w, 0.f);
    float4 uv = *reinterpret_cast<const float4*>(U + c4);

    size_t so = ((size_t)n * NCHUNK + chunk) * C_ + c4;
    float4 aa = *reinterpret_cast<const float4*>(g_SA + so);
    float4 bb = *reinterpret_cast<const float4*>(g_SB + so);

    const int t0 = chunk * CS;
    const size_t base = ((size_t)n * T_ + t0) * C_ + c4;

    #pragma unroll 2
    for (int i = 0; i < CS; i++) {
        const float tr = (float)(T_ - 1 - (t0 + i));
        float4 r = *reinterpret_cast<const float4*>(g_R + base + (size_t)i * C_);
        float4 k = *reinterpret_cast<const float4*>(g_K + base + (size_t)i * C_);
        float4 v = *reinterpret_cast<const float4*>(g_V + base + (size_t)i * C_);

        float4 gv;
        {
            float eu  = __expf(clip_wk(uv.x + k.x));
            float wkv = fmaf(eu, v.x, aa.x) / (bb.x + eu);
            gv.x = f2tf32f(wkv / (1.0f + __expf(-r.x)));
            float e = __expf(clip_wk(fmaf(-wv.x, tr, k.x)));
            aa.x = fmaf(e, v.x, aa.x); bb.x += e;
        }
        {
            float eu  = __expf(clip_wk(uv.y + k.y));
            float wkv = fmaf(eu, v.y, aa.y) / (bb.y + eu);
            gv.y = f2tf32f(wkv / (1.0f + __expf(-r.y)));
            float e = __expf(clip_wk(fmaf(-wv.y, tr, k.y)));
            aa.y = fmaf(e, v.y, aa.y); bb.y += e;
        }
        {
            float eu  = __expf(clip_wk(uv.z + k.z));
            float wkv = fmaf(eu, v.z, aa.z) / (bb.z + eu);
            gv.z = f2tf32f(wkv / (1.0f + __expf(-r.z)));
            float e = __expf(clip_wk(fmaf(-wv.z, tr, k.z)));
            aa.z = fmaf(e, v.z, aa.z); bb.z += e;
        }
        {
            float eu  = __expf(clip_wk(uv.w + k.w));
            float wkv = fmaf(eu, v.w, aa.w) / (bb.w + eu);
            gv.w = f2tf32f(wkv / (1.0f + __expf(-r.w)));
            float e = __expf(clip_wk(fmaf(-wv.w, tr, k.w)));
            aa.w = fmaf(e, v.w, aa.w); bb.w += e;
        }
        *reinterpret_cast<float4*>(g_G + base + (size_t)i * C_) = gv;
    }
}

// ---------------------------------------------------------------------------
// Launch
// ---------------------------------------------------------------------------
extern "C" void kernel_launch(void* const* d_in, const int* in_sizes, int n_in,
                              void* d_out, int out_size)
{
    const float* x   = (const float*)d_in[0];
    const float* Wr  = (const float*)d_in[1];
    const float* br  = (const float*)d_in[2];
    const float* Wk  = (const float*)d_in[3];
    const float* bk  = (const float*)d_in[4];
    const float* Wv  = (const float*)d_in[5];
    const float* bv  = (const float*)d_in[6];
    const float* Wo  = (const float*)d_in[7];
    const float* bo  = (const float*)d_in[8];
    const float* td  = (const float*)d_in[9];
    const float* U   = (const float*)d_in[10];
    float*       out = (float*)d_out;

    // eps constants
    const double EPSd = exp(-1.0 / 12.0);
    const float  er  = (float)(EPSd / 2.0);
    const float  omr = (float)(1.0 - EPSd / 2.0);
    const float  ek  = (float)(EPSd + 0.3 * 1.0 / 11.0);
    const float  omk = (float)(1.0 - (EPSd + 0.3 * 1.0 / 11.0));
    const float  ev  = (float)EPSd;
    const float  omv = (float)(1.0 - EPSd);

    float *XR, *XK, *XV, *Rb, *Kb, *Vb, *Gb, *Wc;
    cudaGetSymbolAddress((void**)&XR, g_XR);
    cudaGetSymbolAddress((void**)&XK, g_XK);
    cudaGetSymbolAddress((void**)&XV, g_XV);
    cudaGetSymbolAddress((void**)&Rb, g_R);
    cudaGetSymbolAddress((void**)&Kb, g_K);
    cudaGetSymbolAddress((void**)&Vb, g_V);
    cudaGetSymbolAddress((void**)&Gb, g_G);
    cudaGetSymbolAddress((void**)&Wc, g_Wc);

    cudaFuncSetAttribute(gemm_tf32, cudaFuncAttributeMaxDynamicSharedMemorySize, GEMM_SMEM);

    // prep: interp + tf32 rounding, weight rounding
    interp_prep<<<(MTOT * C_ / 4 + 255) / 256, 256>>>(x, er, omr, ek, omk, ev, omv);
    weight_prep<<<dim3(C_ * C_ / 4 / 256, 4), 256>>>(Wr, Wk, Wv, Wo);

    // R/K/V projections fused into one launch (z = 0,1,2)
    dim3 rkv_grid(C_ / BN, MTOT / BM, 3);   // (4, 64, 3)
    gemm_tf32<<<rkv_grid, 256, GEMM_SMEM>>>(XR, XK, XV, Wc, br, bk, bv,
                                            Rb, Kb, Vb, /*wsel=*/0);

    // WKV (chunk-parallel cumsum)
    dim3 wgrid(NCHUNK, N_);
    wkv_partial<<<wgrid, 256>>>(td);
    wkv_scan<<<(N_ * C_ + 255) / 256, 256>>>();
    wkv_final<<<wgrid, 256>>>(td, U);

    // output projection (single z)
    dim3 o_grid(C_ / BN, MTOT / BM, 1);
    gemm_tf32<<<o_grid, 256, GEMM_SMEM>>>(Gb, Gb, Gb, Wc, bo, bo, bo,
                                          out, out, out, /*wsel=*/3);
}

// round 16
// speedup vs baseline: 1.3478x; 1.3478x over previous
#include <cuda_runtime.h>
#include <cuda_fp16.h>
#include <math.h>
#include <stdint.h>

// ---------------------------------------------------------------------------
// Problem constants
// ---------------------------------------------------------------------------
#define N_      4
#define T_      2048
#define C_      1024        // = H*HS = attention dim = model dim
#define MTOT    (N_ * T_)   // 8192 rows for the GEMMs
#define NCHUNK  128
#define CS      (T_ / NCHUNK)   // 16 timesteps per chunk

// ---------------------------------------------------------------------------
// Scratch (allocation-free: __device__ globals)
// ---------------------------------------------------------------------------
__device__ __align__(16) __half g_XRh[MTOT * C_];   // fp16 interpolated inputs
__device__ __align__(16) __half g_XKh[MTOT * C_];
__device__ __align__(16) __half g_XVh[MTOT * C_];
__device__ __align__(16) __half g_Gh [MTOT * C_];   // fp16 sigmoid(R)*WKV
__device__ __align__(16) __half g_Wh [4 * C_ * C_]; // fp16 Wr|Wk|Wv|Wo
__device__ float g_R [MTOT * C_];
__device__ float g_K [MTOT * C_];
__device__ float g_V [MTOT * C_];
__device__ float g_SA[N_ * NCHUNK * C_];
__device__ float g_SB[N_ * NCHUNK * C_];

// ---------------------------------------------------------------------------
// Helpers
// ---------------------------------------------------------------------------
__device__ __forceinline__ float clip_wk(float x) {
    return fminf(fmaxf(x, -20.0f), 10.0f);
}

__device__ __forceinline__ void mma_f16(float* d, const uint32_t* a, const uint32_t* b) {
    asm volatile(
        "mma.sync.aligned.m16n8k16.row.col.f32.f16.f16.f32 "
        "{%0,%1,%2,%3}, {%4,%5,%6,%7}, {%8,%9}, {%0,%1,%2,%3};\n"
        : "+f"(d[0]), "+f"(d[1]), "+f"(d[2]), "+f"(d[3])
        : "r"(a[0]), "r"(a[1]), "r"(a[2]), "r"(a[3]), "r"(b[0]), "r"(b[1]));
}

__device__ __forceinline__ void ldm_x4(uint32_t* r, uint32_t saddr) {
    asm volatile("ldmatrix.sync.aligned.m8n8.x4.shared.b16 {%0,%1,%2,%3}, [%4];"
                 : "=r"(r[0]), "=r"(r[1]), "=r"(r[2]), "=r"(r[3]) : "r"(saddr));
}

__device__ __forceinline__ void cp16g(uint32_t saddr, const void* gsrc) {
    asm volatile("cp.async.cg.shared.global [%0], [%1], 16;\n" :: "r"(saddr), "l"(gsrc));
}
__device__ __forceinline__ void cp_commit() { asm volatile("cp.async.commit_group;\n"); }
__device__ __forceinline__ void cp_wait1()  { asm volatile("cp.async.wait_group 1;\n"); }
__device__ __forceinline__ void cp_wait0()  { asm volatile("cp.async.wait_group 0;\n"); }

// ---------------------------------------------------------------------------
// Prep 1: time interpolation + fp16 rounding (4 elems/thread -> 8B stores)
// ---------------------------------------------------------------------------
__global__ void interp_prep(const float* __restrict__ x,
                            float er, float omr,
                            float ek, float omk,
                            float ev, float omv)
{
    int idx4 = blockIdx.x * blockDim.x + threadIdx.x;
    if (idx4 >= MTOT * C_ / 4) return;
    size_t base = (size_t)idx4 * 4;
    int t = (int)((base / C_) % T_);

    float4 p  = make_float4(0.f, 0.f, 0.f, 0.f);
    float4 nx = make_float4(0.f, 0.f, 0.f, 0.f);
    if (t > 0)      p  = *reinterpret_cast<const float4*>(x + base - C_);
    if (t < T_ - 1) nx = *reinterpret_cast<const float4*>(x + base + C_);

    __half2 r0 = __floats2half2_rn(er * p.x + omr * nx.x, er * p.y + omr * nx.y);
    __half2 r1 = __floats2half2_rn(er * p.z + omr * nx.z, er * p.w + omr * nx.w);
    __half2 k0 = __floats2half2_rn(ek * p.x + omk * nx.x, ek * p.y + omk * nx.y);
    __half2 k1 = __floats2half2_rn(ek * p.z + omk * nx.z, ek * p.w + omk * nx.w);
    __half2 v0 = __floats2half2_rn(ev * p.x + omv * nx.x, ev * p.y + omv * nx.y);
    __half2 v1 = __floats2half2_rn(ev * p.z + omv * nx.z, ev * p.w + omv * nx.w);

    *reinterpret_cast<__half2*>(g_XRh + base)     = r0;
    *reinterpret_cast<__half2*>(g_XRh + base + 2) = r1;
    *reinterpret_cast<__half2*>(g_XKh + base)     = k0;
    *reinterpret_cast<__half2*>(g_XKh + base + 2) = k1;
    *reinterpret_cast<__half2*>(g_XVh + base)     = v0;
    *reinterpret_cast<__half2*>(g_XVh + base + 2) = v1;
}

// ---------------------------------------------------------------------------
// Prep 2: convert weights to fp16.  blockIdx.y selects which weight.
// ---------------------------------------------------------------------------
__global__ void weight_prep(const float* __restrict__ w0, const float* __restrict__ w1,
                            const float* __restrict__ w2, const float* __restrict__ w3)
{
    int idx4 = blockIdx.x * blockDim.x + threadIdx.x;
    if (idx4 >= C_ * C_ / 4) return;
    const float* src = (blockIdx.y == 0) ? w0 : (blockIdx.y == 1) ? w1
                     : (blockIdx.y == 2) ? w2 : w3;
    size_t base = (size_t)idx4 * 4;
    float4 v = *reinterpret_cast<const float4*>(src + base);
    __half2 h0 = __floats2half2_rn(v.x, v.y);
    __half2 h1 = __floats2half2_rn(v.z, v.w);
    __half* dst = g_Wh + (size_t)blockIdx.y * C_ * C_ + base;
    *reinterpret_cast<__half2*>(dst)     = h0;
    *reinterpret_cast<__half2*>(dst + 2) = h1;
}

// ---------------------------------------------------------------------------
// FP16 tensor-core GEMM (NT), cp.async 3-stage ring, one barrier per K-tile.
//   C[m,j] = sum_k A[m,k]*W[j,k] + bias[j]   (A, W fp16; acc f32)
//   CTA tile 128x256, BK=64 (=128B rows, SW128 swizzle); 8 warps in a 2x4
//   grid of 64x64 warp tiles (4x8 m16n8k16 fragments via ldmatrix.x4).
//   blockIdx.z selects among up to 3 fused (A, W, bias, Cout) problem sets.
// ---------------------------------------------------------------------------
#define BM 128
#define BN 256
#define BK 64
#define NKT (C_ / BK)            // 16
#define A_BYTES (128 * 128)      // 16 KB
#define B_BYTES (256 * 128)      // 32 KB
#define STAGE_BYTES (A_BYTES + B_BYTES)   // 48 KB
#define NSTAGE 3
#define GEMM_SMEM (NSTAGE * STAGE_BYTES)  // 147456 B

__global__ __launch_bounds__(256, 1)
void gemm_f16(const __half* __restrict__ A0, const __half* __restrict__ A1,
              const __half* __restrict__ A2,
              const __half* __restrict__ Wh,
              const float* __restrict__ b0, const float* __restrict__ b1,
              const float* __restrict__ b2,
              float* __restrict__ C0, float* __restrict__ C1,
              float* __restrict__ C2,
              int wsel)
{
    extern __shared__ __align__(16) char sm[];
    const uint32_t smb = (uint32_t)__cvta_generic_to_shared(sm);

    const int z = blockIdx.z;
    const __half* A    = (z == 0) ? A0 : (z == 1) ? A1 : A2;
    const __half* W    = Wh + (size_t)(wsel + z) * C_ * C_;
    const float*  bias = (z == 0) ? b0 : (z == 1) ? b1 : b2;
    float*        Cout = (z == 0) ? C0 : (z == 1) ? C1 : C2;

    const int K  = C_;
    const int Nn = C_;

    const int tid    = threadIdx.x;
    const int bm     = blockIdx.y * BM;
    const int bn     = blockIdx.x * BN;
    const int warpId = tid >> 5;
    const int lane   = tid & 31;
    const int g      = lane >> 2;           // 0..7
    const int t4     = lane & 3;            // 0..3
    const int wr     = (warpId >> 2) * 64;  // warp row band (2)
    const int wc     = (warpId & 3) * 64;   // warp col band (4)

    // cp.async mapping: A: thread t -> row t/2, chunks (t&1)*4+0..3
    //                   B: thread t -> row t,   chunks 0..7    (chunk = 16B)
    const int arow  = tid >> 1;
    const int acb   = (tid & 1) * 4;
    const __half* Agp = A + (size_t)(bm + arow) * K + acb * 8;
    const __half* Wgp = W + (size_t)(bn + tid) * K;
    uint32_t a_soff[4], b_soff[8];
    #pragma unroll
    for (int i = 0; i < 4; i++) {
        int c = acb + i;
        a_soff[i] = (uint32_t)(arow * 128 + ((c ^ (arow & 7)) << 4));
    }
    #pragma unroll
    for (int c = 0; c < 8; c++)
        b_soff[c] = (uint32_t)(A_BYTES + tid * 128 + ((c ^ (tid & 7)) << 4));

    // ldmatrix per-lane address components
    const int lj  = lane >> 3;      // 0..3 (matrix index)
    const int lr8 = lane & 7;       // row within 8x8

    float acc[4][8][4];
    #pragma unroll
    for (int i = 0; i < 4; i++)
        #pragma unroll
        for (int j = 0; j < 8; j++)
            #pragma unroll
            for (int q = 0; q < 4; q++)
                acc[i][j][q] = 0.0f;

    auto load_stage = [&](int s, int kt) {
        const uint32_t sb = smb + (uint32_t)s * STAGE_BYTES;
        const size_t ko = (size_t)kt * BK;
        #pragma unroll
        for (int i = 0; i < 4; i++)
            cp16g(sb + a_soff[i], Agp + ko + i * 8);
        #pragma unroll
        for (int c = 0; c < 8; c++)
            cp16g(sb + b_soff[c], Wgp + ko + c * 8);
        cp_commit();
    };

    load_stage(0, 0);
    load_stage(1, 1);

    int cur = 0;
    for (int kt = 0; kt < NKT; kt++) {
        if (kt + 1 < NKT) cp_wait1();
        else              cp_wait0();
        __syncthreads();   // data of kt visible AND stage (kt+2)%3 free

        if (kt + 2 < NKT) {
            int nst = cur + 2; if (nst >= NSTAGE) nst -= NSTAGE;
            load_stage(nst, kt + 2);
        }

        const uint32_t sb = smb + (uint32_t)cur * STAGE_BYTES;

        #pragma unroll
        for (int kk = 0; kk < 4; kk++) {          // 4 k16-steps per BK=64
            uint32_t afr[4][4];
            uint32_t bfr[16];
            // A fragments: mt band rows wr+mt*16; matrices (rowblk = j&1, chunk = j>>1)
            #pragma unroll
            for (int mt = 0; mt < 4; mt++) {
                const int row = wr + mt * 16 + ((lj & 1) << 3) + lr8;
                const int ch  = (kk << 1) + (lj >> 1);
                ldm_x4(afr[mt], sb + (uint32_t)(row * 128 + ((ch ^ (row & 7)) << 4)));
            }
            // B fragments: p covers nt=2p,2p+1; matrices (chunk = j&1, rowblk = j>>1)
            #pragma unroll
            for (int p = 0; p < 4; p++) {
                const int row = wc + p * 16 + ((lj >> 1) << 3) + lr8;
                const int ch  = (kk << 1) + (lj & 1);
                ldm_x4(bfr + p * 4,
                       sb + (uint32_t)(A_BYTES + row * 128 + ((ch ^ (row & 7)) << 4)));
            }
            #pragma unroll
            for (int mt = 0; mt < 4; mt++)
                #pragma unroll
                for (int nt = 0; nt < 8; nt++)
                    mma_f16(acc[mt][nt], afr[mt], bfr + nt * 2);
        }

        cur++; if (cur >= NSTAGE) cur = 0;
    }

    // epilogue: bias + store (f32 out)
    #pragma unroll
    for (int mt = 0; mt < 4; mt++) {
        const int row = bm + wr + mt * 16 + g;
        #pragma unroll
        for (int nt = 0; nt < 8; nt++) {
            const int col = bn + wc + nt * 8 + t4 * 2;
            const float b0v = bias[col];
            const float b1v = bias[col + 1];
            float2 v0 = make_float2(acc[mt][nt][0] + b0v, acc[mt][nt][1] + b1v);
            float2 v1 = make_float2(acc[mt][nt][2] + b0v, acc[mt][nt][3] + b1v);
            *reinterpret_cast<float2*>(Cout + (size_t)row * Nn + col) = v0;
            *reinterpret_cast<float2*>(Cout + (size_t)(row + 8) * Nn + col) = v1;
        }
    }
}

// ---------------------------------------------------------------------------
// WKV recurrence (chunk-parallel cumsum, 3 passes).  256 threads, 4 ch/thread.
// ---------------------------------------------------------------------------
__global__ __launch_bounds__(256)
void wkv_partial(const float* __restrict__ td)
{
    const int c4    = threadIdx.x * 4;
    const int chunk = blockIdx.x;
    const int n     = blockIdx.y;

    float4 wv = *reinterpret_cast<const float4*>(td + c4);
    wv.x = fmaxf(wv.x, 0.f); wv.y = fmaxf(wv.y, 0.f);
    wv.z = fmaxf(wv.z, 0.f); wv.w = fmaxf(wv.w, 0.f);

    const int t0 = chunk * CS;
    const size_t base = ((size_t)n * T_ + t0) * C_ + c4;

    float4 sa = make_float4(0.f, 0.f, 0.f, 0.f);
    float4 sb = make_float4(0.f, 0.f, 0.f, 0.f);

    #pragma unroll 4
    for (int i = 0; i < CS; i++) {
        const float tr = (float)(T_ - 1 - (t0 + i));
        float4 k = *reinterpret_cast<const float4*>(g_K + base + (size_t)i * C_);
        float4 v = *reinterpret_cast<const float4*>(g_V + base + (size_t)i * C_);
        float ex = __expf(clip_wk(fmaf(-wv.x, tr, k.x)));
        float ey = __expf(clip_wk(fmaf(-wv.y, tr, k.y)));
        float ez = __expf(clip_wk(fmaf(-wv.z, tr, k.z)));
        float ew = __expf(clip_wk(fmaf(-wv.w, tr, k.w)));
        sa.x = fmaf(ex, v.x, sa.x); sb.x += ex;
        sa.y = fmaf(ey, v.y, sa.y); sb.y += ey;
        sa.z = fmaf(ez, v.z, sa.z); sb.z += ez;
        sa.w = fmaf(ew, v.w, sa.w); sb.w += ew;
    }
    size_t o = ((size_t)n * NCHUNK + chunk) * C_ + c4;
    *reinterpret_cast<float4*>(g_SA + o) = sa;
    *reinterpret_cast<float4*>(g_SB + o) = sb;
}

__global__ void wkv_scan()
{
    int idx = blockIdx.x * blockDim.x + threadIdx.x;   // over N_*C_
    if (idx >= N_ * C_) return;
    int n = idx / C_;
    int c = idx % C_;
    float ra = 0.0f, rb = 0.0f;
    for (int ch = 0; ch < NCHUNK; ch++) {
        size_t o = ((size_t)n * NCHUNK + ch) * C_ + c;
        float ta = g_SA[o], tb = g_SB[o];
        g_SA[o] = ra;                 // exclusive prefix
        g_SB[o] = rb;
        ra += ta;
        rb += tb;
    }
}

__global__ __launch_bounds__(256)
void wkv_final(const float* __restrict__ td, const float* __restrict__ U)
{
    const int c4    = threadIdx.x * 4;
    const int chunk = blockIdx.x;
    const int n     = blockIdx.y;

    float4 wv = *reinterpret_cast<const float4*>(td + c4);
    wv.x = fmaxf(wv.x, 0.f); wv.y = fmaxf(wv.y, 0.f);
    wv.z = fmaxf(wv.z, 0.f); wv.w = fmaxf(wv.w, 0.f);
    float4 uv = *reinterpret_cast<const float4*>(U + c4);

    size_t so = ((size_t)n * NCHUNK + chunk) * C_ + c4;
    float4 aa = *reinterpret_cast<const float4*>(g_SA + so);
    float4 bb = *reinterpret_cast<const float4*>(g_SB + so);

    const int t0 = chunk * CS;
    const size_t base = ((size_t)n * T_ + t0) * C_ + c4;

    #pragma unroll 2
    for (int i = 0; i < CS; i++) {
        const float tr = (float)(T_ - 1 - (t0 + i));
        float4 r = *reinterpret_cast<const float4*>(g_R + base + (size_t)i * C_);
        float4 k = *reinterpret_cast<const float4*>(g_K + base + (size_t)i * C_);
        float4 v = *reinterpret_cast<const float4*>(g_V + base + (size_t)i * C_);

        float4 gv;
        {
            float eu  = __expf(clip_wk(uv.x + k.x));
            float wkv = fmaf(eu, v.x, aa.x) / (bb.x + eu);
            gv.x = wkv / (1.0f + __expf(-r.x));
            float e = __expf(clip_wk(fmaf(-wv.x, tr, k.x)));
            aa.x = fmaf(e, v.x, aa.x); bb.x += e;
        }
        {
            float eu  = __expf(clip_wk(uv.y + k.y));
            float wkv = fmaf(eu, v.y, aa.y) / (bb.y + eu);
            gv.y = wkv / (1.0f + __expf(-r.y));
            float e = __expf(clip_wk(fmaf(-wv.y, tr, k.y)));
            aa.y = fmaf(e, v.y, aa.y); bb.y += e;
        }
        {
            float eu  = __expf(clip_wk(uv.z + k.z));
            float wkv = fmaf(eu, v.z, aa.z) / (bb.z + eu);
            gv.z = wkv / (1.0f + __expf(-r.z));
            float e = __expf(clip_wk(fmaf(-wv.z, tr, k.z)));
            aa.z = fmaf(e, v.z, aa.z); bb.z += e;
        }
        {
            float eu  = __expf(clip_wk(uv.w + k.w));
            float wkv = fmaf(eu, v.w, aa.w) / (bb.w + eu);
            gv.w = wkv / (1.0f + __expf(-r.w));
            float e = __expf(clip_wk(fmaf(-wv.w, tr, k.w)));
            aa.w = fmaf(e, v.w, aa.w); bb.w += e;
        }
        __half2 h0 = __floats2half2_rn(gv.x, gv.y);
        __half2 h1 = __floats2half2_rn(gv.z, gv.w);
        *reinterpret_cast<__half2*>(g_Gh + base + (size_t)i * C_)     = h0;
        *reinterpret_cast<__half2*>(g_Gh + base + (size_t)i * C_ + 2) = h1;
    }
}

// ---------------------------------------------------------------------------
// Launch
// ---------------------------------------------------------------------------
extern "C" void kernel_launch(void* const* d_in, const int* in_sizes, int n_in,
                              void* d_out, int out_size)
{
    const float* x   = (const float*)d_in[0];
    const float* Wr  = (const float*)d_in[1];
    const float* br  = (const float*)d_in[2];
    const float* Wk  = (const float*)d_in[3];
    const float* bk  = (const float*)d_in[4];
    const float* Wv  = (const float*)d_in[5];
    const float* bv  = (const float*)d_in[6];
    const float* Wo  = (const float*)d_in[7];
    const float* bo  = (const float*)d_in[8];
    const float* td  = (const float*)d_in[9];
    const float* U   = (const float*)d_in[10];
    float*       out = (float*)d_out;

    // eps constants
    const double EPSd = exp(-1.0 / 12.0);
    const float  er  = (float)(EPSd / 2.0);
    const float  omr = (float)(1.0 - EPSd / 2.0);
    const float  ek  = (float)(EPSd + 0.3 * 1.0 / 11.0);
    const float  omk = (float)(1.0 - (EPSd + 0.3 * 1.0 / 11.0));
    const float  ev  = (float)EPSd;
    const float  omv = (float)(1.0 - EPSd);

    __half *XR, *XK, *XV, *Gh, *Wh;
    float *Rb, *Kb, *Vb;
    cudaGetSymbolAddress((void**)&XR, g_XRh);
    cudaGetSymbolAddress((void**)&XK, g_XKh);
    cudaGetSymbolAddress((void**)&XV, g_XVh);
    cudaGetSymbolAddress((void**)&Gh, g_Gh);
    cudaGetSymbolAddress((void**)&Wh, g_Wh);
    cudaGetSymbolAddress((void**)&Rb, g_R);
    cudaGetSymbolAddress((void**)&Kb, g_K);
    cudaGetSymbolAddress((void**)&Vb, g_V);

    cudaFuncSetAttribute(gemm_f16, cudaFuncAttributeMaxDynamicSharedMemorySize, GEMM_SMEM);

    // prep: interp + fp16 conversion, weight conversion
    interp_prep<<<(MTOT * C_ / 4 + 255) / 256, 256>>>(x, er, omr, ek, omk, ev, omv);
    weight_prep<<<dim3(C_ * C_ / 4 / 256, 4), 256>>>(Wr, Wk, Wv, Wo);

    // R/K/V projections fused into one launch (z = 0,1,2)
    dim3 rkv_grid(C_ / BN, MTOT / BM, 3);   // (4, 64, 3)
    gemm_f16<<<rkv_grid, 256, GEMM_SMEM>>>(XR, XK, XV, Wh, br, bk, bv,
                                           Rb, Kb, Vb, /*wsel=*/0);

    // WKV (chunk-parallel cumsum)
    dim3 wgrid(NCHUNK, N_);
    wkv_partial<<<wgrid, 256>>>(td);
    wkv_scan<<<(N_ * C_ + 255) / 256, 256>>>();
    wkv_final<<<wgrid, 256>>>(td, U);

    // output projection (single z)
    dim3 o_grid(C_ / BN, MTOT / BM, 1);
    gemm_f16<<<o_grid, 256, GEMM_SMEM>>>(Gh, Gh, Gh, Wh, bo, bo, bo,
                                         out, out, out, /*wsel=*/3);
}

// round 17
// speedup vs baseline: 1.6636x; 1.2343x over previous
#include <cuda_runtime.h>
#include <cuda_fp16.h>
#include <math.h>
#include <stdint.h>

// ---------------------------------------------------------------------------
// Problem constants
// ---------------------------------------------------------------------------
#define N_      4
#define T_      2048
#define C_      1024        // = H*HS = attention dim = model dim
#define MTOT    (N_ * T_)   // 8192 rows for the GEMMs
#define NCHUNK  128
#define CS      (T_ / NCHUNK)   // 16 timesteps per chunk

// ---------------------------------------------------------------------------
// Scratch (allocation-free: __device__ globals)
// ---------------------------------------------------------------------------
__device__ __align__(16) __half g_XRh[MTOT * C_];   // fp16 interpolated inputs
__device__ __align__(16) __half g_XKh[MTOT * C_];
__device__ __align__(16) __half g_XVh[MTOT * C_];
__device__ __align__(16) __half g_Gh [MTOT * C_];   // fp16 sigmoid(R)*WKV
__device__ __align__(16) __half g_Wh [4 * C_ * C_]; // fp16 Wr|Wk|Wv|Wo
__device__ float g_R [MTOT * C_];
__device__ float g_K [MTOT * C_];
__device__ float g_V [MTOT * C_];
__device__ float g_SA[N_ * NCHUNK * C_];
__device__ float g_SB[N_ * NCHUNK * C_];

// ---------------------------------------------------------------------------
// Helpers
// ---------------------------------------------------------------------------
__device__ __forceinline__ float clip_wk(float x) {
    return fminf(fmaxf(x, -20.0f), 10.0f);
}

__device__ __forceinline__ void mma_f16(float* d, const uint32_t* a, const uint32_t* b) {
    asm volatile(
        "mma.sync.aligned.m16n8k16.row.col.f32.f16.f16.f32 "
        "{%0,%1,%2,%3}, {%4,%5,%6,%7}, {%8,%9}, {%0,%1,%2,%3};\n"
        : "+f"(d[0]), "+f"(d[1]), "+f"(d[2]), "+f"(d[3])
        : "r"(a[0]), "r"(a[1]), "r"(a[2]), "r"(a[3]), "r"(b[0]), "r"(b[1]));
}

__device__ __forceinline__ void ldm_x4(uint32_t* r, uint32_t saddr) {
    asm volatile("ldmatrix.sync.aligned.m8n8.x4.shared.b16 {%0,%1,%2,%3}, [%4];"
                 : "=r"(r[0]), "=r"(r[1]), "=r"(r[2]), "=r"(r[3]) : "r"(saddr));
}

__device__ __forceinline__ void cp16g(uint32_t saddr, const void* gsrc) {
    asm volatile("cp.async.cg.shared.global [%0], [%1], 16;\n" :: "r"(saddr), "l"(gsrc));
}
__device__ __forceinline__ void cp_commit() { asm volatile("cp.async.commit_group;\n"); }
__device__ __forceinline__ void cp_wait1()  { asm volatile("cp.async.wait_group 1;\n"); }
__device__ __forceinline__ void cp_wait0()  { asm volatile("cp.async.wait_group 0;\n"); }

// ---------------------------------------------------------------------------
// Prep 1: time interpolation + fp16 rounding (4 elems/thread -> 8B stores)
// ---------------------------------------------------------------------------
__global__ void interp_prep(const float* __restrict__ x,
                            float er, float omr,
                            float ek, float omk,
                            float ev, float omv)
{
    int idx4 = blockIdx.x * blockDim.x + threadIdx.x;
    if (idx4 >= MTOT * C_ / 4) return;
    size_t base = (size_t)idx4 * 4;
    int t = (int)((base / C_) % T_);

    float4 p  = make_float4(0.f, 0.f, 0.f, 0.f);
    float4 nx = make_float4(0.f, 0.f, 0.f, 0.f);
    if (t > 0)      p  = *reinterpret_cast<const float4*>(x + base - C_);
    if (t < T_ - 1) nx = *reinterpret_cast<const float4*>(x + base + C_);

    __half2 r0 = __floats2half2_rn(er * p.x + omr * nx.x, er * p.y + omr * nx.y);
    __half2 r1 = __floats2half2_rn(er * p.z + omr * nx.z, er * p.w + omr * nx.w);
    __half2 k0 = __floats2half2_rn(ek * p.x + omk * nx.x, ek * p.y + omk * nx.y);
    __half2 k1 = __floats2half2_rn(ek * p.z + omk * nx.z, ek * p.w + omk * nx.w);
    __half2 v0 = __floats2half2_rn(ev * p.x + omv * nx.x, ev * p.y + omv * nx.y);
    __half2 v1 = __floats2half2_rn(ev * p.z + omv * nx.z, ev * p.w + omv * nx.w);

    *reinterpret_cast<__half2*>(g_XRh + base)     = r0;
    *reinterpret_cast<__half2*>(g_XRh + base + 2) = r1;
    *reinterpret_cast<__half2*>(g_XKh + base)     = k0;
    *reinterpret_cast<__half2*>(g_XKh + base + 2) = k1;
    *reinterpret_cast<__half2*>(g_XVh + base)     = v0;
    *reinterpret_cast<__half2*>(g_XVh + base + 2) = v1;
}

// ---------------------------------------------------------------------------
// Prep 2: convert weights to fp16.  blockIdx.y selects which weight.
// ---------------------------------------------------------------------------
__global__ void weight_prep(const float* __restrict__ w0, const float* __restrict__ w1,
                            const float* __restrict__ w2, const float* __restrict__ w3)
{
    int idx4 = blockIdx.x * blockDim.x + threadIdx.x;
    if (idx4 >= C_ * C_ / 4) return;
    const float* src = (blockIdx.y == 0) ? w0 : (blockIdx.y == 1) ? w1
                     : (blockIdx.y == 2) ? w2 : w3;
    size_t base = (size_t)idx4 * 4;
    float4 v = *reinterpret_cast<const float4*>(src + base);
    __half2 h0 = __floats2half2_rn(v.x, v.y);
    __half2 h1 = __floats2half2_rn(v.z, v.w);
    __half* dst = g_Wh + (size_t)blockIdx.y * C_ * C_ + base;
    *reinterpret_cast<__half2*>(dst)     = h0;
    *reinterpret_cast<__half2*>(dst + 2) = h1;
}

// ---------------------------------------------------------------------------
// FP16 tensor-core GEMM (NT), cp.async 3-stage ring, one barrier per K-tile.
//   C[m,j] = sum_k A[m,k]*W[j,k] + bias[j]   (A, W fp16; acc f32)
//   CTA tile 128x128, BK=64 (=128B rows, SW128 swizzle); 8 warps in a 2x4
//   grid of 64x32 warp tiles (4x4 m16n8k16 fragments via ldmatrix.x4).
//   96KB smem/CTA -> 2 CTAs/SM (4 warps/SMSP + cross-CTA overlap).
//   blockIdx.z selects among up to 3 fused (A, W, bias, Cout) problem sets.
// ---------------------------------------------------------------------------
#define BM 128
#define BN 128
#define BK 64
#define NKT (C_ / BK)            // 16
#define A_BYTES (128 * 128)      // 16 KB
#define B_BYTES (128 * 128)      // 16 KB
#define STAGE_BYTES (A_BYTES + B_BYTES)   // 32 KB
#define NSTAGE 3
#define GEMM_SMEM (NSTAGE * STAGE_BYTES)  // 98304 B

__global__ __launch_bounds__(256, 2)
void gemm_f16(const __half* __restrict__ A0, const __half* __restrict__ A1,
              const __half* __restrict__ A2,
              const __half* __restrict__ Wh,
              const float* __restrict__ b0, const float* __restrict__ b1,
              const float* __restrict__ b2,
              float* __restrict__ C0, float* __restrict__ C1,
              float* __restrict__ C2,
              int wsel)
{
    extern __shared__ __align__(16) char sm[];
    const uint32_t smb = (uint32_t)__cvta_generic_to_shared(sm);

    const int z = blockIdx.z;
    const __half* A    = (z == 0) ? A0 : (z == 1) ? A1 : A2;
    const __half* W    = Wh + (size_t)(wsel + z) * C_ * C_;
    const float*  bias = (z == 0) ? b0 : (z == 1) ? b1 : b2;
    float*        Cout = (z == 0) ? C0 : (z == 1) ? C1 : C2;

    const int K  = C_;
    const int Nn = C_;

    const int tid    = threadIdx.x;
    const int bm     = blockIdx.y * BM;
    const int bn     = blockIdx.x * BN;
    const int warpId = tid >> 5;
    const int lane   = tid & 31;
    const int g      = lane >> 2;           // 0..7
    const int t4     = lane & 3;            // 0..3
    const int wr     = (warpId >> 2) * 64;  // warp row band (2)
    const int wc     = (warpId & 3) * 32;   // warp col band (4)

    // cp.async: thread t -> row t/2, chunks (t&1)*4+0..3 (chunk = 16B) for A and B
    const int arow  = tid >> 1;
    const int acb   = (tid & 1) * 4;
    const __half* Agp = A + (size_t)(bm + arow) * K + acb * 8;
    const __half* Wgp = W + (size_t)(bn + arow) * K + acb * 8;
    uint32_t a_soff[4], b_soff[4];
    #pragma unroll
    for (int i = 0; i < 4; i++) {
        int c = acb + i;
        uint32_t sw = (uint32_t)(arow * 128 + ((c ^ (arow & 7)) << 4));
        a_soff[i] = sw;
        b_soff[i] = A_BYTES + sw;
    }

    // ldmatrix per-lane address components
    const int lj  = lane >> 3;      // 0..3 (matrix index)
    const int lr8 = lane & 7;       // row within 8x8

    float acc[4][4][4];
    #pragma unroll
    for (int i = 0; i < 4; i++)
        #pragma unroll
        for (int j = 0; j < 4; j++)
            #pragma unroll
            for (int q = 0; q < 4; q++)
                acc[i][j][q] = 0.0f;

    auto load_stage = [&](int s, int kt) {
        const uint32_t sb = smb + (uint32_t)s * STAGE_BYTES;
        const size_t ko = (size_t)kt * BK;
        #pragma unroll
        for (int i = 0; i < 4; i++)
            cp16g(sb + a_soff[i], Agp + ko + i * 8);
        #pragma unroll
        for (int i = 0; i < 4; i++)
            cp16g(sb + b_soff[i], Wgp + ko + i * 8);
        cp_commit();
    };

    load_stage(0, 0);
    load_stage(1, 1);

    int cur = 0;
    for (int kt = 0; kt < NKT; kt++) {
        if (kt + 1 < NKT) cp_wait1();
        else              cp_wait0();
        __syncthreads();   // data of kt visible AND stage (kt+2)%3 free

        if (kt + 2 < NKT) {
            int nst = cur + 2; if (nst >= NSTAGE) nst -= NSTAGE;
            load_stage(nst, kt + 2);
        }

        const uint32_t sb = smb + (uint32_t)cur * STAGE_BYTES;

        #pragma unroll
        for (int kk = 0; kk < 4; kk++) {          // 4 k16-steps per BK=64
            uint32_t afr[4][4];
            uint32_t bfr[8];
            // A fragments: rows wr+mt*16; matrices (rowblk = j&1, chunk = j>>1)
            #pragma unroll
            for (int mt = 0; mt < 4; mt++) {
                const int row = wr + mt * 16 + ((lj & 1) << 3) + lr8;
                const int ch  = (kk << 1) + (lj >> 1);
                ldm_x4(afr[mt], sb + (uint32_t)(row * 128 + ((ch ^ (row & 7)) << 4)));
            }
            // B fragments: p covers nt=2p,2p+1; matrices (chunk = j&1, rowblk = j>>1)
            #pragma unroll
            for (int p = 0; p < 2; p++) {
                const int row = wc + p * 16 + ((lj >> 1) << 3) + lr8;
                const int ch  = (kk << 1) + (lj & 1);
                ldm_x4(bfr + p * 4,
                       sb + (uint32_t)(A_BYTES + row * 128 + ((ch ^ (row & 7)) << 4)));
            }
            #pragma unroll
            for (int mt = 0; mt < 4; mt++)
                #pragma unroll
                for (int nt = 0; nt < 4; nt++)
                    mma_f16(acc[mt][nt], afr[mt], bfr + nt * 2);
        }

        cur++; if (cur >= NSTAGE) cur = 0;
    }

    // epilogue: bias + store (f32 out)
    #pragma unroll
    for (int mt = 0; mt < 4; mt++) {
        const int row = bm + wr + mt * 16 + g;
        #pragma unroll
        for (int nt = 0; nt < 4; nt++) {
            const int col = bn + wc + nt * 8 + t4 * 2;
            const float b0v = bias[col];
            const float b1v = bias[col + 1];
            float2 v0 = make_float2(acc[mt][nt][0] + b0v, acc[mt][nt][1] + b1v);
            float2 v1 = make_float2(acc[mt][nt][2] + b0v, acc[mt][nt][3] + b1v);
            *reinterpret_cast<float2*>(Cout + (size_t)row * Nn + col) = v0;
            *reinterpret_cast<float2*>(Cout + (size_t)(row + 8) * Nn + col) = v1;
        }
    }
}

// ---------------------------------------------------------------------------
// WKV recurrence (chunk-parallel cumsum, 3 passes).  256 threads, 4 ch/thread.
// ---------------------------------------------------------------------------
__global__ __launch_bounds__(256)
void wkv_partial(const float* __restrict__ td)
{
    const int c4    = threadIdx.x * 4;
    const int chunk = blockIdx.x;
    const int n     = blockIdx.y;

    float4 wv = *reinterpret_cast<const float4*>(td + c4);
    wv.x = fmaxf(wv.x, 0.f); wv.y = fmaxf(wv.y, 0.f);
    wv.z = fmaxf(wv.z, 0.f); wv.w = fmaxf(wv.w, 0.f);

    const int t0 = chunk * CS;
    const size_t base = ((size_t)n * T_ + t0) * C_ + c4;

    float4 sa = make_float4(0.f, 0.f, 0.f, 0.f);
    float4 sb = make_float4(0.f, 0.f, 0.f, 0.f);

    #pragma unroll 4
    for (int i = 0; i < CS; i++) {
        const float tr = (float)(T_ - 1 - (t0 + i));
        float4 k = *reinterpret_cast<const float4*>(g_K + base + (size_t)i * C_);
        float4 v = *reinterpret_cast<const float4*>(g_V + base + (size_t)i * C_);
        float ex = __expf(clip_wk(fmaf(-wv.x, tr, k.x)));
        float ey = __expf(clip_wk(fmaf(-wv.y, tr, k.y)));
        float ez = __expf(clip_wk(fmaf(-wv.z, tr, k.z)));
        float ew = __expf(clip_wk(fmaf(-wv.w, tr, k.w)));
        sa.x = fmaf(ex, v.x, sa.x); sb.x += ex;
        sa.y = fmaf(ey, v.y, sa.y); sb.y += ey;
        sa.z = fmaf(ez, v.z, sa.z); sb.z += ez;
        sa.w = fmaf(ew, v.w, sa.w); sb.w += ew;
    }
    size_t o = ((size_t)n * NCHUNK + chunk) * C_ + c4;
    *reinterpret_cast<float4*>(g_SA + o) = sa;
    *reinterpret_cast<float4*>(g_SB + o) = sb;
}

__global__ void wkv_scan()
{
    int idx = blockIdx.x * blockDim.x + threadIdx.x;   // over N_*C_
    if (idx >= N_ * C_) return;
    int n = idx / C_;
    int c = idx % C_;
    float ra = 0.0f, rb = 0.0f;
    for (int ch = 0; ch < NCHUNK; ch++) {
        size_t o = ((size_t)n * NCHUNK + ch) * C_ + c;
        float ta = g_SA[o], tb = g_SB[o];
        g_SA[o] = ra;                 // exclusive prefix
        g_SB[o] = rb;
        ra += ta;
        rb += tb;
    }
}

__global__ __launch_bounds__(256)
void wkv_final(const float* __restrict__ td, const float* __restrict__ U)
{
    const int c4    = threadIdx.x * 4;
    const int chunk = blockIdx.x;
    const int n     = blockIdx.y;

    float4 wv = *reinterpret_cast<const float4*>(td + c4);
    wv.x = fmaxf(wv.x, 0.f); wv.y = fmaxf(wv.y, 0.f);
    wv.z = fmaxf(wv.z, 0.f); wv.w = fmaxf(wv.w, 0.f);
    float4 uv = *reinterpret_cast<const float4*>(U + c4);

    size_t so = ((size_t)n * NCHUNK + chunk) * C_ + c4;
    float4 aa = *reinterpret_cast<const float4*>(g_SA + so);
    float4 bb = *reinterpret_cast<const float4*>(g_SB + so);

    const int t0 = chunk * CS;
    const size_t base = ((size_t)n * T_ + t0) * C_ + c4;

    #pragma unroll 2
    for (int i = 0; i < CS; i++) {
        const float tr = (float)(T_ - 1 - (t0 + i));
        float4 r = *reinterpret_cast<const float4*>(g_R + base + (size_t)i * C_);
        float4 k = *reinterpret_cast<const float4*>(g_K + base + (size_t)i * C_);
        float4 v = *reinterpret_cast<const float4*>(g_V + base + (size_t)i * C_);

        float4 gv;
        {
            float eu  = __expf(clip_wk(uv.x + k.x));
            float wkv = fmaf(eu, v.x, aa.x) / (bb.x + eu);
            gv.x = wkv / (1.0f + __expf(-r.x));
            float e = __expf(clip_wk(fmaf(-wv.x, tr, k.x)));
            aa.x = fmaf(e, v.x, aa.x); bb.x += e;
        }
        {
            float eu  = __expf(clip_wk(uv.y + k.y));
            float wkv = fmaf(eu, v.y, aa.y) / (bb.y + eu);
            gv.y = wkv / (1.0f + __expf(-r.y));
            float e = __expf(clip_wk(fmaf(-wv.y, tr, k.y)));
            aa.y = fmaf(e, v.y, aa.y); bb.y += e;
        }
        {
            float eu  = __expf(clip_wk(uv.z + k.z));
            float wkv = fmaf(eu, v.z, aa.z) / (bb.z + eu);
            gv.z = wkv / (1.0f + __expf(-r.z));
            float e = __expf(clip_wk(fmaf(-wv.z, tr, k.z)));
            aa.z = fmaf(e, v.z, aa.z); bb.z += e;
        }
        {
            float eu  = __expf(clip_wk(uv.w + k.w));
            float wkv = fmaf(eu, v.w, aa.w) / (bb.w + eu);
            gv.w = wkv / (1.0f + __expf(-r.w));
            float e = __expf(clip_wk(fmaf(-wv.w, tr, k.w)));
            aa.w = fmaf(e, v.w, aa.w); bb.w += e;
        }
        __half2 h0 = __floats2half2_rn(gv.x, gv.y);
        __half2 h1 = __floats2half2_rn(gv.z, gv.w);
        *reinterpret_cast<__half2*>(g_Gh + base + (size_t)i * C_)     = h0;
        *reinterpret_cast<__half2*>(g_Gh + base + (size_t)i * C_ + 2) = h1;
    }
}

// ---------------------------------------------------------------------------
// Launch
// ---------------------------------------------------------------------------
extern "C" void kernel_launch(void* const* d_in, const int* in_sizes, int n_in,
                              void* d_out, int out_size)
{
    const float* x   = (const float*)d_in[0];
    const float* Wr  = (const float*)d_in[1];
    const float* br  = (const float*)d_in[2];
    const float* Wk  = (const float*)d_in[3];
    const float* bk  = (const float*)d_in[4];
    const float* Wv  = (const float*)d_in[5];
    const float* bv  = (const float*)d_in[6];
    const float* Wo  = (const float*)d_in[7];
    const float* bo  = (const float*)d_in[8];
    const float* td  = (const float*)d_in[9];
    const float* U   = (const float*)d_in[10];
    float*       out = (float*)d_out;

    // eps constants
    const double EPSd = exp(-1.0 / 12.0);
    const float  er  = (float)(EPSd / 2.0);
    const float  omr = (float)(1.0 - EPSd / 2.0);
    const float  ek  = (float)(EPSd + 0.3 * 1.0 / 11.0);
    const float  omk = (float)(1.0 - (EPSd + 0.3 * 1.0 / 11.0));
    const float  ev  = (float)EPSd;
    const float  omv = (float)(1.0 - EPSd);

    __half *XR, *XK, *XV, *Gh, *Wh;
    float *Rb, *Kb, *Vb;
    cudaGetSymbolAddress((void**)&XR, g_XRh);
    cudaGetSymbolAddress((void**)&XK, g_XKh);
    cudaGetSymbolAddress((void**)&XV, g_XVh);
    cudaGetSymbolAddress((void**)&Gh, g_Gh);
    cudaGetSymbolAddress((void**)&Wh, g_Wh);
    cudaGetSymbolAddress((void**)&Rb, g_R);
    cudaGetSymbolAddress((void**)&Kb, g_K);
    cudaGetSymbolAddress((void**)&Vb, g_V);

    cudaFuncSetAttribute(gemm_f16, cudaFuncAttributeMaxDynamicSharedMemorySize, GEMM_SMEM);

    // prep: interp + fp16 conversion, weight conversion
    interp_prep<<<(MTOT * C_ / 4 + 255) / 256, 256>>>(x, er, omr, ek, omk, ev, omv);
    weight_prep<<<dim3(C_ * C_ / 4 / 256, 4), 256>>>(Wr, Wk, Wv, Wo);

    // R/K/V projections fused into one launch (z = 0,1,2)
    dim3 rkv_grid(C_ / BN, MTOT / BM, 3);   // (8, 64, 3)
    gemm_f16<<<rkv_grid, 256, GEMM_SMEM>>>(XR, XK, XV, Wh, br, bk, bv,
                                           Rb, Kb, Vb, /*wsel=*/0);

    // WKV (chunk-parallel cumsum)
    dim3 wgrid(NCHUNK, N_);
    wkv_partial<<<wgrid, 256>>>(td);
    wkv_scan<<<(N_ * C_ + 255) / 256, 256>>>();
    wkv_final<<<wgrid, 256>>>(td, U);

    // output projection (single z)
    dim3 o_grid(C_ / BN, MTOT / BM, 1);
    gemm_f16<<<o_grid, 256, GEMM_SMEM>>>(Gh, Gh, Gh, Wh, bo, bo, bo,
                                         out, out, out, /*wsel=*/3);
}